// round 12
// baseline (speedup 1.0000x reference)
#include <cuda_runtime.h>
#include <cstdint>

// ---------------------------------------------------------------------------
// Problem shape (fixed by the reference):
//   x      : [4, 2048, 4096] fp32  -> M = 8192, K = 4096
//   weight : [4096, 4096]    fp32  -> N = 4096 (row-major [N, K], K contiguous)
//   bias   : [4096]          fp32
//   out    : [8192, 4096]    fp32
// ---------------------------------------------------------------------------
#define M_DIM 8192
#define N_DIM 4096
#define K_DIM 4096

// Scratch (allocation-free rule: __device__ globals)
__device__ __align__(256) signed char g_qx[(size_t)M_DIM * K_DIM];  // 32 MB
__device__ __align__(256) signed char g_qw[(size_t)N_DIM * K_DIM];  // 16 MB
__device__ unsigned g_amax[2];  // [0] = amax(|x|) bits, [1] = amax(|w|) bits

// ---------------------------------------------------------------------------
// Stage 0: reset amax accumulators (runs every replay -> deterministic)
// ---------------------------------------------------------------------------
__global__ void hx_init() {
    g_amax[0] = 0u;
    g_amax[1] = 0u;
}

// ---------------------------------------------------------------------------
// Stage 1: amax reduction. For non-negative floats the IEEE bit pattern is
// monotonic in value, so unsigned max over fabs bit patterns == float max.
// ---------------------------------------------------------------------------
__global__ void hx_amax(const float4* __restrict__ src, int n4, int which) {
    unsigned m = 0u;
    const int stride = gridDim.x * blockDim.x;
    for (int i = blockIdx.x * blockDim.x + threadIdx.x; i < n4; i += stride) {
        float4 v = src[i];
        m = max(m, __float_as_uint(fabsf(v.x)));
        m = max(m, __float_as_uint(fabsf(v.y)));
        m = max(m, __float_as_uint(fabsf(v.z)));
        m = max(m, __float_as_uint(fabsf(v.w)));
    }
#pragma unroll
    for (int o = 16; o > 0; o >>= 1)
        m = max(m, __shfl_xor_sync(0xffffffffu, m, o));
    __shared__ unsigned red[8];
    if ((threadIdx.x & 31) == 0) red[threadIdx.x >> 5] = m;
    __syncthreads();
    if (threadIdx.x == 0) {
        unsigned v = red[0];
#pragma unroll
        for (int i = 1; i < 8; ++i) v = max(v, red[i]);
        atomicMax(&g_amax[which], v);
    }
}

// ---------------------------------------------------------------------------
// Stage 2: quantize.  q = clip(rint(x * (127/amax)), -127, 127)  as int8.
// rintf is round-half-to-even == jnp.round, matching the reference exactly.
// ---------------------------------------------------------------------------
__global__ void hx_quant(const float4* __restrict__ src, int n4, int which) {
    char4* __restrict__ dst =
        reinterpret_cast<char4*>(which ? g_qw : g_qx);
    const float s = 127.0f / __uint_as_float(g_amax[which]);
    const int stride = gridDim.x * blockDim.x;
    for (int i = blockIdx.x * blockDim.x + threadIdx.x; i < n4; i += stride) {
        float4 v = src[i];
        char4 q;
        q.x = (signed char)(int)fminf(127.f, fmaxf(-127.f, rintf(v.x * s)));
        q.y = (signed char)(int)fminf(127.f, fmaxf(-127.f, rintf(v.y * s)));
        q.z = (signed char)(int)fminf(127.f, fmaxf(-127.f, rintf(v.z * s)));
        q.w = (signed char)(int)fminf(127.f, fmaxf(-127.f, rintf(v.w * s)));
        dst[i] = q;
    }
}

// ---------------------------------------------------------------------------
// Stage 3: int8 GEMM (TN): out[m][n] = sum_k qx[m][k] * qw[n][k]
// Block tile 128x128x128, 8 warps (2 M x 4 N), warp tile 64x32,
// mma.sync.m16n8k32.s8 with ldmatrix feeds, cp.async double buffering.
//
// SMEM layout (per tile, per stage): 128 rows x 128 bytes (dense, BK=128).
// Swizzle: 16B chunk index c (0..7) stored at c ^ (row & 7). Any 8
// consecutive aligned rows hit 8 distinct 16B lines mod 128B ->
// conflict-free ldmatrix.x4 for both operands.
// ---------------------------------------------------------------------------
#define BM 128
#define BN 128
#define BK 128
#define STAGE_BYTES (BM * BK)          // 16384
#define B_OFF (2 * STAGE_BYTES)       // A[2] then B[2]
#define SMEM_BYTES (4 * STAGE_BYTES)  // 65536

__device__ __forceinline__ void cp16(uint32_t dst, const void* src) {
    asm volatile("cp.async.cg.shared.global [%0], [%1], 16;\n" ::"r"(dst), "l"(src));
}
__device__ __forceinline__ void cp_commit() {
    asm volatile("cp.async.commit_group;\n" ::: "memory");
}
template <int N_>
__device__ __forceinline__ void cp_wait() {
    asm volatile("cp.async.wait_group %0;\n" ::"n"(N_) : "memory");
}
__device__ __forceinline__ void ldsm4(uint32_t addr, uint32_t& r0, uint32_t& r1,
                                      uint32_t& r2, uint32_t& r3) {
    asm volatile("ldmatrix.sync.aligned.m8n8.x4.shared.b16 {%0,%1,%2,%3}, [%4];\n"
                 : "=r"(r0), "=r"(r1), "=r"(r2), "=r"(r3)
                 : "r"(addr));
}
__device__ __forceinline__ void imma(int* c, const uint32_t* a, const uint32_t* b) {
    asm volatile(
        "mma.sync.aligned.m16n8k32.row.col.s32.s8.s8.s32 "
        "{%0,%1,%2,%3}, {%4,%5,%6,%7}, {%8,%9}, {%0,%1,%2,%3};\n"
        : "+r"(c[0]), "+r"(c[1]), "+r"(c[2]), "+r"(c[3])
        : "r"(a[0]), "r"(a[1]), "r"(a[2]), "r"(a[3]), "r"(b[0]), "r"(b[1]));
}

__global__ void __launch_bounds__(256, 2)
hx_gemm(const float* __restrict__ bias, float* __restrict__ out) {
    extern __shared__ signed char smem[];
    const uint32_t sbase = (uint32_t)__cvta_generic_to_shared(smem);

    const int t = threadIdx.x;
    const int lane = t & 31;
    const int warp = t >> 5;
    const int wm = warp >> 2;  // 0..1  (M)
    const int wn = warp & 3;   // 0..3  (N)
    const int m0 = blockIdx.y * BM;
    const int n0 = blockIdx.x * BN;

    int acc[4][4][4];
#pragma unroll
    for (int a = 0; a < 4; ++a)
#pragma unroll
        for (int b = 0; b < 4; ++b)
#pragma unroll
            for (int r = 0; r < 4; ++r) acc[a][b][r] = 0;

    const signed char* gA = g_qx + (size_t)m0 * K_DIM;
    const signed char* gB = g_qw + (size_t)n0 * K_DIM;

    // cp.async chunk mapping: thread t handles (row = t>>3 + 32p, chunk = t&7)
    const int lrow = t >> 3;
    const int lc = t & 7;

    auto load_stage = [&](int k0, int buf) {
        const uint32_t abase = sbase + buf * STAGE_BYTES;
        const uint32_t bbase = sbase + B_OFF + buf * STAGE_BYTES;
#pragma unroll
        for (int p = 0; p < 4; ++p) {
            const int row = lrow + p * 32;
            const uint32_t off = row * 128 + ((lc ^ (row & 7)) << 4);
            cp16(abase + off, gA + (size_t)row * K_DIM + k0 + (lc << 4));
            cp16(bbase + off, gB + (size_t)row * K_DIM + k0 + (lc << 4));
        }
    };

    auto compute_stage = [&](int buf) {
        const uint32_t abase = sbase + buf * STAGE_BYTES;
        const uint32_t bbase = sbase + B_OFF + buf * STAGE_BYTES;
#pragma unroll
        for (int ks = 0; ks < 4; ++ks) {
            uint32_t a[4][4];
#pragma unroll
            for (int mf = 0; mf < 4; ++mf) {
                // ldmatrix x4 tiles: [rows+0..7,k0-15][rows+8..15,k0-15]
                //                    [rows+0..7,k16-31][rows+8..15,k16-31]
                const int row = wm * 64 + mf * 16 + (lane & 7) + ((lane >> 3) & 1) * 8;
                const int kb = ks * 32 + (lane >> 4) * 16;
                const uint32_t addr =
                    abase + row * 128 + (((kb >> 4) ^ (row & 7)) << 4);
                ldsm4(addr, a[mf][0], a[mf][1], a[mf][2], a[mf][3]);
            }
            uint32_t b[4][2];
#pragma unroll
            for (int p = 0; p < 2; ++p) {
                // tiles: [nf=2p,k0-15][nf=2p,k16-31][nf=2p+1,k0-15][nf=2p+1,k16-31]
                const int nr = wn * 32 + (p * 2 + (lane >> 4)) * 8 + (lane & 7);
                const int kb = ks * 32 + ((lane >> 3) & 1) * 16;
                const uint32_t addr =
                    bbase + nr * 128 + (((kb >> 4) ^ (nr & 7)) << 4);
                ldsm4(addr, b[2 * p][0], b[2 * p][1], b[2 * p + 1][0], b[2 * p + 1][1]);
            }
#pragma unroll
            for (int mf = 0; mf < 4; ++mf)
#pragma unroll
                for (int nf = 0; nf < 4; ++nf) imma(acc[mf][nf], a[mf], b[nf]);
        }
    };

    load_stage(0, 0);
    cp_commit();

    const int NIT = K_DIM / BK;  // 32
    int buf = 0;
    for (int it = 0; it < NIT; ++it) {
        if (it + 1 < NIT) {
            load_stage((it + 1) * BK, buf ^ 1);
            cp_commit();
            cp_wait<1>();
        } else {
            cp_wait<0>();
        }
        __syncthreads();
        compute_stage(buf);
        __syncthreads();
        buf ^= 1;
    }

    // Epilogue: out = acc * (1/(sx*sw)) + bias   (<=2 ulp vs reference divide)
    const float sx = 127.0f / __uint_as_float(g_amax[0]);
    const float sw = 127.0f / __uint_as_float(g_amax[1]);
    const float invd = 1.0f / (sx * sw);

#pragma unroll
    for (int mf = 0; mf < 4; ++mf) {
        const int r0 = m0 + wm * 64 + mf * 16 + (lane >> 2);
#pragma unroll
        for (int nf = 0; nf < 4; ++nf) {
            const int cg = n0 + wn * 32 + nf * 8 + 2 * (lane & 3);
            const float2 bz = *reinterpret_cast<const float2*>(bias + cg);
            float2 o0, o1;
            o0.x = (float)acc[mf][nf][0] * invd + bz.x;
            o0.y = (float)acc[mf][nf][1] * invd + bz.y;
            o1.x = (float)acc[mf][nf][2] * invd + bz.x;
            o1.y = (float)acc[mf][nf][3] * invd + bz.y;
            *reinterpret_cast<float2*>(out + (size_t)r0 * N_DIM + cg) = o0;
            *reinterpret_cast<float2*>(out + (size_t)(r0 + 8) * N_DIM + cg) = o1;
        }
    }
}

// ---------------------------------------------------------------------------
// Launch: init -> amax(x), amax(w) -> quant(x), quant(w) -> gemm
// All on the capture stream; ordering via stream dependencies.
// ---------------------------------------------------------------------------
extern "C" void kernel_launch(void* const* d_in, const int* in_sizes, int n_in,
                              void* d_out, int out_size) {
    const float* x = (const float*)d_in[0];
    const float* w = (const float*)d_in[1];
    const float* bias = (const float*)d_in[2];
    float* out = (float*)d_out;
    (void)in_sizes; (void)n_in; (void)out_size;

    cudaFuncSetAttribute(hx_gemm, cudaFuncAttributeMaxDynamicSharedMemorySize,
                         SMEM_BYTES);

    hx_init<<<1, 1>>>();

    const int nx4 = (M_DIM * K_DIM) / 4;  // 8388608
    const int nw4 = (N_DIM * K_DIM) / 4;  // 4194304
    hx_amax<<<2048, 256>>>((const float4*)x, nx4, 0);
    hx_amax<<<1024, 256>>>((const float4*)w, nw4, 1);

    hx_quant<<<2048, 256>>>((const float4*)x, nx4, 0);
    hx_quant<<<1024, 256>>>((const float4*)w, nw4, 1);

    dim3 grid(N_DIM / BN, M_DIM / BM);  // (32, 64)
    hx_gemm<<<grid, 256, SMEM_BYTES>>>(bias, out);
}

// round 14
// speedup vs baseline: 1.0425x; 1.0425x over previous
#include <cuda_runtime.h>
#include <cstdint>

// ---------------------------------------------------------------------------
// x      : [4, 2048, 4096] fp32  -> M = 8192, K = 4096
// weight : [4096, 4096]    fp32  -> N = 4096 (row-major [N, K], K contiguous)
// bias   : [4096]          fp32
// out    : [8192, 4096]    fp32
// ---------------------------------------------------------------------------
#define M_DIM 8192
#define N_DIM 4096
#define K_DIM 4096

#define BM 128
#define BN 256
#define BK 128
#define NS 4
#define NIT (K_DIM / BK)              // 32
#define A_STAGE (BM * BK)             // 16384
#define B_STAGE (BN * BK)             // 32768
#define B_OFF (NS * A_STAGE)          // 65536
#define SMEM_TC (NS * (A_STAGE + B_STAGE))  // 196608
#define STAGE_BYTES_TX (A_STAGE + B_STAGE)  // 49152

// Scratch in pre-swizzled tile-major layout (allocation-free rule).
// A: [mb=64][kb=32][row=128][swizzled 128B]   (32 MB)
// B: [nb=16][kb=32][row=256][swizzled 128B]   (16 MB)
__device__ __align__(256) signed char g_qx[(size_t)M_DIM * K_DIM];
__device__ __align__(256) signed char g_qw[(size_t)N_DIM * K_DIM];
__device__ unsigned g_amax[2];

// ---------------------------------------------------------------------------
__global__ void hx_init() {
    g_amax[0] = 0u;
    g_amax[1] = 0u;
}

// amax: bit-pattern max over |x| is exact for non-negative IEEE floats
__global__ void hx_amax(const float4* __restrict__ src, int n4, int which) {
    unsigned m = 0u;
    const int stride = gridDim.x * blockDim.x;
    for (int i = blockIdx.x * blockDim.x + threadIdx.x; i < n4; i += stride) {
        float4 v = src[i];
        m = max(m, __float_as_uint(fabsf(v.x)));
        m = max(m, __float_as_uint(fabsf(v.y)));
        m = max(m, __float_as_uint(fabsf(v.z)));
        m = max(m, __float_as_uint(fabsf(v.w)));
    }
#pragma unroll
    for (int o = 16; o > 0; o >>= 1)
        m = max(m, __shfl_xor_sync(0xffffffffu, m, o));
    __shared__ unsigned red[8];
    if ((threadIdx.x & 31) == 0) red[threadIdx.x >> 5] = m;
    __syncthreads();
    if (threadIdx.x == 0) {
        unsigned v = red[0];
#pragma unroll
        for (int i = 1; i < 8; ++i) v = max(v, red[i]);
        atomicMax(&g_amax[which], v);
    }
}

// ---------------------------------------------------------------------------
// Quantize + pre-swizzle into tile-major layout.
// q = clip(rint(v * 127/amax), -127, 127); rintf == jnp.round (half-even).
// ---------------------------------------------------------------------------
__device__ __forceinline__ unsigned pack4(float4 v, float s) {
    int a = (int)fminf(127.f, fmaxf(-127.f, rintf(v.x * s)));
    int b = (int)fminf(127.f, fmaxf(-127.f, rintf(v.y * s)));
    int c = (int)fminf(127.f, fmaxf(-127.f, rintf(v.z * s)));
    int d = (int)fminf(127.f, fmaxf(-127.f, rintf(v.w * s)));
    return (a & 255) | ((b & 255) << 8) | ((c & 255) << 16) | ((d & 255) << 24);
}

// A: thread = (row r of 8192, 16B chunk cc of 256)
__global__ void hx_quantA(const float4* __restrict__ x) {
    const int tid = blockIdx.x * blockDim.x + threadIdx.x;
    const int r = tid >> 8, cc = tid & 255;
    const float s = 127.0f / __uint_as_float(g_amax[0]);
    const float4* p = x + (size_t)r * 1024 + cc * 4;
    uint4 q;
    q.x = pack4(p[0], s); q.y = pack4(p[1], s);
    q.z = pack4(p[2], s); q.w = pack4(p[3], s);
    const int mb = r >> 7, row = r & 127, kb = cc >> 3, c = cc & 7;
    const size_t off =
        ((size_t)((mb * 32 + kb) * 128 + row)) * 128 + ((c ^ (row & 7)) << 4);
    *reinterpret_cast<uint4*>(g_qx + off) = q;
}

// B: thread = (row r of 4096, 16B chunk cc of 256); 256-row blocks
__global__ void hx_quantB(const float4* __restrict__ w) {
    const int tid = blockIdx.x * blockDim.x + threadIdx.x;
    const int r = tid >> 8, cc = tid & 255;
    const float s = 127.0f / __uint_as_float(g_amax[1]);
    const float4* p = w + (size_t)r * 1024 + cc * 4;
    uint4 q;
    q.x = pack4(p[0], s); q.y = pack4(p[1], s);
    q.z = pack4(p[2], s); q.w = pack4(p[3], s);
    const int nb = r >> 8, row = r & 255, kb = cc >> 3, c = cc & 7;
    const size_t off =
        ((size_t)((nb * 32 + kb) * 256 + row)) * 128 + ((c ^ (row & 7)) << 4);
    *reinterpret_cast<uint4*>(g_qw + off) = q;
}

// ---------------------------------------------------------------------------
// Int8 GEMM: IMMA compute, cp.async.bulk feed (tiles are contiguous +
// pre-swizzled in GMEM). CTA 128x256, BK=128, 4 stages, 8 compute warps
// (warp tile 64x64) + 1 producer thread, mbarrier full/empty ring.
// ---------------------------------------------------------------------------
__device__ __forceinline__ void ldsm4(uint32_t addr, uint32_t& r0, uint32_t& r1,
                                      uint32_t& r2, uint32_t& r3) {
    asm volatile("ldmatrix.sync.aligned.m8n8.x4.shared.b16 {%0,%1,%2,%3}, [%4];\n"
                 : "=r"(r0), "=r"(r1), "=r"(r2), "=r"(r3)
                 : "r"(addr));
}
__device__ __forceinline__ void imma(int* c, const uint32_t* a, const uint32_t* b) {
    asm volatile(
        "mma.sync.aligned.m16n8k32.row.col.s32.s8.s8.s32 "
        "{%0,%1,%2,%3}, {%4,%5,%6,%7}, {%8,%9}, {%0,%1,%2,%3};\n"
        : "+r"(c[0]), "+r"(c[1]), "+r"(c[2]), "+r"(c[3])
        : "r"(a[0]), "r"(a[1]), "r"(a[2]), "r"(a[3]), "r"(b[0]), "r"(b[1]));
}
__device__ __forceinline__ void bar_init(uint32_t bar, uint32_t cnt) {
    asm volatile("mbarrier.init.shared.b64 [%0], %1;" ::"r"(bar), "r"(cnt) : "memory");
}
__device__ __forceinline__ void bar_arrive(uint32_t bar) {
    asm volatile("mbarrier.arrive.shared.b64 _, [%0];" ::"r"(bar) : "memory");
}
__device__ __forceinline__ void bar_expect_tx(uint32_t bar, uint32_t bytes) {
    asm volatile("mbarrier.arrive.expect_tx.shared.b64 _, [%0], %1;"
                 ::"r"(bar), "r"(bytes) : "memory");
}
__device__ __forceinline__ void bar_wait(uint32_t bar, uint32_t parity) {
    asm volatile(
        "{\n\t.reg .pred P;\n\t"
        "BW_%=:\n\t"
        "mbarrier.try_wait.parity.acquire.cta.shared::cta.b64 P, [%0], %1, 0x989680;\n\t"
        "@P bra.uni BD_%=;\n\t"
        "bra.uni BW_%=;\n\t"
        "BD_%=:\n\t}"
        ::"r"(bar), "r"(parity) : "memory");
}
__device__ __forceinline__ void bulk_cp(uint32_t dst, const void* src,
                                        uint32_t bytes, uint32_t bar) {
    asm volatile(
        "cp.async.bulk.shared::cluster.global.mbarrier::complete_tx::bytes "
        "[%0], [%1], %2, [%3];"
        ::"r"(dst), "l"(src), "r"(bytes), "r"(bar) : "memory");
}

__global__ void __launch_bounds__(288, 1)
hx_gemm(const float* __restrict__ bias, float* __restrict__ out) {
    extern __shared__ signed char smem[];
    __shared__ __align__(8) uint64_t s_bars[2 * NS];  // full[4], empty[4]

    const uint32_t sbase = (uint32_t)__cvta_generic_to_shared(smem);
    const uint32_t bar0 = (uint32_t)__cvta_generic_to_shared(&s_bars[0]);

    const int t = threadIdx.x;
    const int lane = t & 31;
    const int wid = t >> 5;
    const int m0 = blockIdx.y * BM;
    const int n0 = blockIdx.x * BN;

    if (t == 0) {
#pragma unroll
        for (int s = 0; s < NS; ++s) {
            bar_init(bar0 + 8 * s, 1);            // full[s]: producer expect_tx
            bar_init(bar0 + 8 * (NS + s), 256);   // empty[s]: 256 consumer arrivals
        }
    }
    __syncthreads();

    // ---------------- producer: thread 256 -----------------------------------
    if (t == 256) {
        const signed char* gA = g_qx + (size_t)blockIdx.y * 32 * A_STAGE;
        const signed char* gB = g_qw + (size_t)blockIdx.x * 32 * B_STAGE;
        for (int i = 0; i < NIT; ++i) {
            const int s = i & (NS - 1);
            bar_wait(bar0 + 8 * (NS + s), 1u ^ ((i >> 2) & 1));  // empty[s]
            const uint32_t fb = bar0 + 8 * s;
            bar_expect_tx(fb, STAGE_BYTES_TX);
            const uint32_t ab = sbase + s * A_STAGE;
            const uint32_t bb = sbase + B_OFF + s * B_STAGE;
            const signed char* sa = gA + (size_t)i * A_STAGE;
            const signed char* sb = gB + (size_t)i * B_STAGE;
            bulk_cp(ab, sa, 8192, fb);
            bulk_cp(ab + 8192, sa + 8192, 8192, fb);
#pragma unroll
            for (int j = 0; j < 4; ++j)
                bulk_cp(bb + j * 8192, sb + j * 8192, 8192, fb);
        }
    }

    // ---------------- consumers: warps 0..7, warp tile 64x64 -----------------
    if (wid < 8) {
        const int wm = wid >> 2;  // 0..1
        const int wn = wid & 3;   // 0..3

        int acc[4][8][4];
#pragma unroll
        for (int a = 0; a < 4; ++a)
#pragma unroll
            for (int b = 0; b < 8; ++b)
#pragma unroll
                for (int r = 0; r < 4; ++r) acc[a][b][r] = 0;

        for (int i = 0; i < NIT; ++i) {
            const int s = i & (NS - 1);
            bar_wait(bar0 + 8 * s, (i >> 2) & 1);  // full[s]
            const uint32_t abase = sbase + s * A_STAGE;
            const uint32_t bbase = sbase + B_OFF + s * B_STAGE;
#pragma unroll
            for (int ks = 0; ks < 4; ++ks) {
                uint32_t a[4][4];
#pragma unroll
                for (int mf = 0; mf < 4; ++mf) {
                    const int row =
                        wm * 64 + mf * 16 + (lane & 7) + ((lane >> 3) & 1) * 8;
                    const int kb = ks * 32 + (lane >> 4) * 16;
                    const uint32_t addr =
                        abase + row * 128 + (((kb >> 4) ^ (row & 7)) << 4);
                    ldsm4(addr, a[mf][0], a[mf][1], a[mf][2], a[mf][3]);
                }
                uint32_t b[8][2];
#pragma unroll
                for (int p = 0; p < 4; ++p) {
                    const int nr = wn * 64 + (p * 2 + (lane >> 4)) * 8 + (lane & 7);
                    const int kb = ks * 32 + ((lane >> 3) & 1) * 16;
                    const uint32_t addr =
                        bbase + nr * 128 + (((kb >> 4) ^ (nr & 7)) << 4);
                    ldsm4(addr, b[2 * p][0], b[2 * p][1], b[2 * p + 1][0],
                          b[2 * p + 1][1]);
                }
#pragma unroll
                for (int mf = 0; mf < 4; ++mf)
#pragma unroll
                    for (int nf = 0; nf < 8; ++nf) imma(acc[mf][nf], a[mf], b[nf]);
            }
            bar_arrive(bar0 + 8 * (NS + s));  // empty[s]
        }

        // ---- epilogue: out = acc * invd + bias ----
        const float sx = 127.0f / __uint_as_float(g_amax[0]);
        const float sw = 127.0f / __uint_as_float(g_amax[1]);
        const float invd = 1.0f / (sx * sw);

#pragma unroll
        for (int mf = 0; mf < 4; ++mf) {
            const int r0 = m0 + wm * 64 + mf * 16 + (lane >> 2);
#pragma unroll
            for (int nf = 0; nf < 8; ++nf) {
                const int cg = n0 + wn * 64 + nf * 8 + 2 * (lane & 3);
                const float2 bz = *reinterpret_cast<const float2*>(bias + cg);
                float2 o0, o1;
                o0.x = (float)acc[mf][nf][0] * invd + bz.x;
                o0.y = (float)acc[mf][nf][1] * invd + bz.y;
                o1.x = (float)acc[mf][nf][2] * invd + bz.x;
                o1.y = (float)acc[mf][nf][3] * invd + bz.y;
                *reinterpret_cast<float2*>(out + (size_t)r0 * N_DIM + cg) = o0;
                *reinterpret_cast<float2*>(out + (size_t)(r0 + 8) * N_DIM + cg) = o1;
            }
        }
    }
}

// ---------------------------------------------------------------------------
extern "C" void kernel_launch(void* const* d_in, const int* in_sizes, int n_in,
                              void* d_out, int out_size) {
    const float* x = (const float*)d_in[0];
    const float* w = (const float*)d_in[1];
    const float* bias = (const float*)d_in[2];
    float* out = (float*)d_out;
    (void)in_sizes; (void)n_in; (void)out_size;

    cudaFuncSetAttribute(hx_gemm, cudaFuncAttributeMaxDynamicSharedMemorySize,
                         SMEM_TC);

    hx_init<<<1, 1>>>();

    const int nx4 = (M_DIM * K_DIM) / 4;
    const int nw4 = (N_DIM * K_DIM) / 4;
    hx_amax<<<2048, 256>>>((const float4*)x, nx4, 0);
    hx_amax<<<1024, 256>>>((const float4*)w, nw4, 1);

    hx_quantA<<<(M_DIM * 256) / 256, 256>>>((const float4*)x);
    hx_quantB<<<(N_DIM * 256) / 256, 256>>>((const float4*)w);

    dim3 grid(N_DIM / BN, M_DIM / BM);  // (16, 64)
    hx_gemm<<<grid, 288, SMEM_TC>>>(bias, out);
}

// round 15
// speedup vs baseline: 2.9512x; 2.8309x over previous
#include <cuda_runtime.h>
#include <cstdint>

// ---------------------------------------------------------------------------
// x      : [4, 2048, 4096] fp32  -> M = 8192, K = 4096
// weight : [4096, 4096]    fp32  -> N = 4096 (row-major [N, K], K contiguous)
// bias   : [4096]          fp32
// out    : [8192, 4096]    fp32
//
// Quantize to int8 values, but carry them as bf16 and run the GEMM on the
// legacy bf16 HMMA path (m16n8k16, f32 accum). All values are small integers,
// so fp32 accumulation is bit-exact vs the reference int32 MAC.
// ---------------------------------------------------------------------------
#define M_DIM 8192
#define N_DIM 4096
#define K_DIM 4096

#define BM 128
#define BN 256
#define BK 64                          // 64 bf16 = 128B per row
#define NS 4
#define NIT (K_DIM / BK)               // 64
#define A_STAGE (BM * 128)             // 16384 bytes
#define B_STAGE (BN * 128)             // 32768 bytes
#define B_OFF (NS * A_STAGE)           // 65536
#define SMEM_TC (NS * (A_STAGE + B_STAGE))  // 196608
#define STAGE_BYTES_TX (A_STAGE + B_STAGE)  // 49152

// Scratch: pre-swizzled tile-major bf16 (allocation-free rule).
// A: [mb=64][kb=64][row=128][128B swizzled]  = 64 MB
// B: [nb=16][kb=64][row=256][128B swizzled]  = 32 MB
__device__ __align__(256) unsigned short g_qxb[(size_t)M_DIM * K_DIM];
__device__ __align__(256) unsigned short g_qwb[(size_t)N_DIM * K_DIM];
__device__ unsigned g_amax[2];

// ---------------------------------------------------------------------------
__global__ void hx_init() {
    g_amax[0] = 0u;
    g_amax[1] = 0u;
}

// amax: bit-pattern max over |x| is exact for non-negative IEEE floats
__global__ void hx_amax(const float4* __restrict__ src, int n4, int which) {
    unsigned m = 0u;
    const int stride = gridDim.x * blockDim.x;
    for (int i = blockIdx.x * blockDim.x + threadIdx.x; i < n4; i += stride) {
        float4 v = src[i];
        m = max(m, __float_as_uint(fabsf(v.x)));
        m = max(m, __float_as_uint(fabsf(v.y)));
        m = max(m, __float_as_uint(fabsf(v.z)));
        m = max(m, __float_as_uint(fabsf(v.w)));
    }
#pragma unroll
    for (int o = 16; o > 0; o >>= 1)
        m = max(m, __shfl_xor_sync(0xffffffffu, m, o));
    __shared__ unsigned red[8];
    if ((threadIdx.x & 31) == 0) red[threadIdx.x >> 5] = m;
    __syncthreads();
    if (threadIdx.x == 0) {
        unsigned v = red[0];
#pragma unroll
        for (int i = 1; i < 8; ++i) v = max(v, red[i]);
        atomicMax(&g_amax[which], v);
    }
}

// ---------------------------------------------------------------------------
// Quantize to integer-valued bf16, pre-swizzled tile-major.
// q = clip(rint(v * 127/amax), -127, 127); rintf == jnp.round (half-even).
// Integers in [-127,127] are exactly representable in bf16.
// ---------------------------------------------------------------------------
__device__ __forceinline__ float qval(float v, float s) {
    return fminf(127.f, fmaxf(-127.f, rintf(v * s)));
}
__device__ __forceinline__ uint32_t bf2(float lo, float hi) {
    uint32_t r;
    asm("cvt.rn.bf16x2.f32 %0, %1, %2;" : "=r"(r) : "f"(hi), "f"(lo));
    return r;
}
__device__ __forceinline__ uint4 pack8(float4 a, float4 b, float s) {
    uint4 q;
    q.x = bf2(qval(a.x, s), qval(a.y, s));
    q.y = bf2(qval(a.z, s), qval(a.w, s));
    q.z = bf2(qval(b.x, s), qval(b.y, s));
    q.w = bf2(qval(b.z, s), qval(b.w, s));
    return q;
}

// A: thread = (row r of 8192, 16B out-chunk cc of 512)
__global__ void hx_quantA(const float4* __restrict__ x) {
    const int tid = blockIdx.x * blockDim.x + threadIdx.x;
    const int r = tid >> 9, cc = tid & 511;
    const float s = 127.0f / __uint_as_float(g_amax[0]);
    const float4* p = x + (size_t)r * 1024 + cc * 2;
    const uint4 q = pack8(p[0], p[1], s);
    const int mb = r >> 7, row = r & 127, kb = cc >> 3, c = cc & 7;
    const size_t off =
        ((size_t)((mb * 64 + kb) * 128 + row)) * 128 + ((c ^ (row & 7)) << 4);
    *reinterpret_cast<uint4*>(reinterpret_cast<char*>(g_qxb) + off) = q;
}

// B: thread = (row r of 4096, 16B out-chunk cc of 512); 256-row blocks
__global__ void hx_quantB(const float4* __restrict__ w) {
    const int tid = blockIdx.x * blockDim.x + threadIdx.x;
    const int r = tid >> 9, cc = tid & 511;
    const float s = 127.0f / __uint_as_float(g_amax[1]);
    const float4* p = w + (size_t)r * 1024 + cc * 2;
    const uint4 q = pack8(p[0], p[1], s);
    const int nb = r >> 8, row = r & 255, kb = cc >> 3, c = cc & 7;
    const size_t off =
        ((size_t)((nb * 64 + kb) * 256 + row)) * 128 + ((c ^ (row & 7)) << 4);
    *reinterpret_cast<uint4*>(reinterpret_cast<char*>(g_qwb) + off) = q;
}

// ---------------------------------------------------------------------------
// bf16 GEMM: HMMA m16n8k16 f32-accum, cp.async.bulk feed of pre-swizzled
// contiguous tiles. CTA 128x256, BK=64, 4 stages, 8 compute warps
// (warp tile 64x64) + 1 producer thread, mbarrier full/empty ring.
// ---------------------------------------------------------------------------
__device__ __forceinline__ void ldsm4(uint32_t addr, uint32_t& r0, uint32_t& r1,
                                      uint32_t& r2, uint32_t& r3) {
    asm volatile("ldmatrix.sync.aligned.m8n8.x4.shared.b16 {%0,%1,%2,%3}, [%4];\n"
                 : "=r"(r0), "=r"(r1), "=r"(r2), "=r"(r3)
                 : "r"(addr));
}
__device__ __forceinline__ void hmma(float* c, const uint32_t* a, const uint32_t* b) {
    asm volatile(
        "mma.sync.aligned.m16n8k16.row.col.f32.bf16.bf16.f32 "
        "{%0,%1,%2,%3}, {%4,%5,%6,%7}, {%8,%9}, {%0,%1,%2,%3};\n"
        : "+f"(c[0]), "+f"(c[1]), "+f"(c[2]), "+f"(c[3])
        : "r"(a[0]), "r"(a[1]), "r"(a[2]), "r"(a[3]), "r"(b[0]), "r"(b[1]));
}
__device__ __forceinline__ void bar_init(uint32_t bar, uint32_t cnt) {
    asm volatile("mbarrier.init.shared.b64 [%0], %1;" ::"r"(bar), "r"(cnt) : "memory");
}
__device__ __forceinline__ void bar_arrive(uint32_t bar) {
    asm volatile("mbarrier.arrive.shared.b64 _, [%0];" ::"r"(bar) : "memory");
}
__device__ __forceinline__ void bar_expect_tx(uint32_t bar, uint32_t bytes) {
    asm volatile("mbarrier.arrive.expect_tx.shared.b64 _, [%0], %1;"
                 ::"r"(bar), "r"(bytes) : "memory");
}
__device__ __forceinline__ void bar_wait(uint32_t bar, uint32_t parity) {
    asm volatile(
        "{\n\t.reg .pred P;\n\t"
        "BW_%=:\n\t"
        "mbarrier.try_wait.parity.acquire.cta.shared::cta.b64 P, [%0], %1, 0x989680;\n\t"
        "@P bra.uni BD_%=;\n\t"
        "bra.uni BW_%=;\n\t"
        "BD_%=:\n\t}"
        ::"r"(bar), "r"(parity) : "memory");
}
__device__ __forceinline__ void bulk_cp(uint32_t dst, const void* src,
                                        uint32_t bytes, uint32_t bar) {
    asm volatile(
        "cp.async.bulk.shared::cluster.global.mbarrier::complete_tx::bytes "
        "[%0], [%1], %2, [%3];"
        ::"r"(dst), "l"(src), "r"(bytes), "r"(bar) : "memory");
}

__global__ void __launch_bounds__(288, 1)
hx_gemm(const float* __restrict__ bias, float* __restrict__ out) {
    extern __shared__ signed char smem[];
    __shared__ __align__(8) uint64_t s_bars[2 * NS];  // full[4], empty[4]

    const uint32_t sbase = (uint32_t)__cvta_generic_to_shared(smem);
    const uint32_t bar0 = (uint32_t)__cvta_generic_to_shared(&s_bars[0]);

    const int t = threadIdx.x;
    const int lane = t & 31;
    const int wid = t >> 5;
    const int m0 = blockIdx.y * BM;
    const int n0 = blockIdx.x * BN;

    if (t == 0) {
#pragma unroll
        for (int s = 0; s < NS; ++s) {
            bar_init(bar0 + 8 * s, 1);            // full[s]: producer expect_tx
            bar_init(bar0 + 8 * (NS + s), 256);   // empty[s]: 256 consumer arrivals
        }
    }
    __syncthreads();

    // ---------------- producer: thread 256 -----------------------------------
    if (t == 256) {
        const char* gA = reinterpret_cast<const char*>(g_qxb) +
                         (size_t)blockIdx.y * 64 * A_STAGE;
        const char* gB = reinterpret_cast<const char*>(g_qwb) +
                         (size_t)blockIdx.x * 64 * B_STAGE;
        for (int i = 0; i < NIT; ++i) {
            const int s = i & (NS - 1);
            bar_wait(bar0 + 8 * (NS + s), 1u ^ ((i >> 2) & 1));  // empty[s]
            const uint32_t fb = bar0 + 8 * s;
            bar_expect_tx(fb, STAGE_BYTES_TX);
            const uint32_t ab = sbase + s * A_STAGE;
            const uint32_t bb = sbase + B_OFF + s * B_STAGE;
            const char* sa = gA + (size_t)i * A_STAGE;
            const char* sb = gB + (size_t)i * B_STAGE;
            bulk_cp(ab, sa, 8192, fb);
            bulk_cp(ab + 8192, sa + 8192, 8192, fb);
#pragma unroll
            for (int j = 0; j < 4; ++j)
                bulk_cp(bb + j * 8192, sb + j * 8192, 8192, fb);
        }
    }

    // ---------------- consumers: warps 0..7, warp tile 64x64 -----------------
    if (wid < 8) {
        const int wm = wid >> 2;  // 0..1
        const int wn = wid & 3;   // 0..3

        float acc[4][8][4];
#pragma unroll
        for (int a = 0; a < 4; ++a)
#pragma unroll
            for (int b = 0; b < 8; ++b)
#pragma unroll
                for (int r = 0; r < 4; ++r) acc[a][b][r] = 0.0f;

        for (int i = 0; i < NIT; ++i) {
            const int s = i & (NS - 1);
            bar_wait(bar0 + 8 * s, (i >> 2) & 1);  // full[s]
            const uint32_t abase = sbase + s * A_STAGE;
            const uint32_t bbase = sbase + B_OFF + s * B_STAGE;
#pragma unroll
            for (int ks = 0; ks < 4; ++ks) {  // 4 x k16 per BK=64
                uint32_t a[4][4];
#pragma unroll
                for (int mf = 0; mf < 4; ++mf) {
                    const int row =
                        wm * 64 + mf * 16 + (lane & 7) + ((lane >> 3) & 1) * 8;
                    const int kc = ks * 2 + (lane >> 4);  // 16B chunk
                    const uint32_t addr =
                        abase + row * 128 + ((kc ^ (row & 7)) << 4);
                    ldsm4(addr, a[mf][0], a[mf][1], a[mf][2], a[mf][3]);
                }
                uint32_t b[8][2];
#pragma unroll
                for (int p = 0; p < 4; ++p) {
                    const int nr = wn * 64 + (p * 2 + (lane >> 4)) * 8 + (lane & 7);
                    const int kc = ks * 2 + ((lane >> 3) & 1);
                    const uint32_t addr =
                        bbase + nr * 128 + ((kc ^ (nr & 7)) << 4);
                    ldsm4(addr, b[2 * p][0], b[2 * p][1], b[2 * p + 1][0],
                          b[2 * p + 1][1]);
                }
#pragma unroll
                for (int mf = 0; mf < 4; ++mf)
#pragma unroll
                    for (int nf = 0; nf < 8; ++nf) hmma(acc[mf][nf], a[mf], b[nf]);
            }
            bar_arrive(bar0 + 8 * (NS + s));  // empty[s]
        }

        // ---- epilogue: out = acc * invd + bias (acc is integer-valued) ----
        const float sx = 127.0f / __uint_as_float(g_amax[0]);
        const float sw = 127.0f / __uint_as_float(g_amax[1]);
        const float invd = 1.0f / (sx * sw);

#pragma unroll
        for (int mf = 0; mf < 4; ++mf) {
            const int r0 = m0 + wm * 64 + mf * 16 + (lane >> 2);
#pragma unroll
            for (int nf = 0; nf < 8; ++nf) {
                const int cg = n0 + wn * 64 + nf * 8 + 2 * (lane & 3);
                const float2 bz = *reinterpret_cast<const float2*>(bias + cg);
                float2 o0, o1;
                o0.x = acc[mf][nf][0] * invd + bz.x;
                o0.y = acc[mf][nf][1] * invd + bz.y;
                o1.x = acc[mf][nf][2] * invd + bz.x;
                o1.y = acc[mf][nf][3] * invd + bz.y;
                *reinterpret_cast<float2*>(out + (size_t)r0 * N_DIM + cg) = o0;
                *reinterpret_cast<float2*>(out + (size_t)(r0 + 8) * N_DIM + cg) = o1;
            }
        }
    }
}

// ---------------------------------------------------------------------------
extern "C" void kernel_launch(void* const* d_in, const int* in_sizes, int n_in,
                              void* d_out, int out_size) {
    const float* x = (const float*)d_in[0];
    const float* w = (const float*)d_in[1];
    const float* bias = (const float*)d_in[2];
    float* out = (float*)d_out;
    (void)in_sizes; (void)n_in; (void)out_size;

    cudaFuncSetAttribute(hx_gemm, cudaFuncAttributeMaxDynamicSharedMemorySize,
                         SMEM_TC);

    hx_init<<<1, 1>>>();

    const int nx4 = (M_DIM * K_DIM) / 4;
    const int nw4 = (N_DIM * K_DIM) / 4;
    hx_amax<<<2048, 256>>>((const float4*)x, nx4, 0);
    hx_amax<<<1024, 256>>>((const float4*)w, nw4, 1);

    hx_quantA<<<(M_DIM * 512) / 256, 256>>>((const float4*)x);
    hx_quantB<<<(N_DIM * 512) / 256, 256>>>((const float4*)w);

    dim3 grid(N_DIM / BN, M_DIM / BM);  // (16, 64)
    hx_gemm<<<grid, 288, SMEM_TC>>>(bias, out);
}

// round 16
// speedup vs baseline: 2.9518x; 1.0002x over previous
#include <cuda_runtime.h>
#include <cstdint>

// ---------------------------------------------------------------------------
// x      : [4, 2048, 4096] fp32  -> M = 8192, K = 4096
// weight : [4096, 4096]    fp32  -> N = 4096 (row-major [N, K], K contiguous)
// bias   : [4096]          fp32
// out    : [8192, 4096]    fp32
//
// Quantize to int8 values carried as bf16; GEMM on legacy bf16 HMMA
// (m16n8k16, f32 accum) — bit-exact vs the int32 MAC for this value range.
// ---------------------------------------------------------------------------
#define M_DIM 8192
#define N_DIM 4096
#define K_DIM 4096

#define BM 128
#define BN 128
#define BK 64                          // 64 bf16 = 128B per row
#define NS 3
#define NIT (K_DIM / BK)               // 64
#define A_STAGE (BM * 128)             // 16384 bytes
#define B_STAGE (BN * 128)             // 16384 bytes
#define B_OFF (NS * A_STAGE)           // 49152
#define SMEM_TC (NS * (A_STAGE + B_STAGE))  // 98304 -> 2 CTAs/SM
#define STAGE_BYTES_TX (A_STAGE + B_STAGE)  // 32768

// Scratch: pre-swizzled tile-major bf16 (allocation-free rule).
// A: [mb=64][kb=64][row=128][128B swizzled]  = 64 MB
// B: [nb=32][kb=64][row=128][128B swizzled]  = 32 MB
__device__ __align__(256) unsigned short g_qxb[(size_t)M_DIM * K_DIM];
__device__ __align__(256) unsigned short g_qwb[(size_t)N_DIM * K_DIM];
__device__ unsigned g_amax[2];

// ---------------------------------------------------------------------------
__global__ void hx_init() {
    g_amax[0] = 0u;
    g_amax[1] = 0u;
}

// amax: bit-pattern max over |x| is exact for non-negative IEEE floats
__global__ void hx_amax(const float4* __restrict__ src, int n4, int which) {
    unsigned m = 0u;
    const int stride = gridDim.x * blockDim.x;
    for (int i = blockIdx.x * blockDim.x + threadIdx.x; i < n4; i += stride) {
        float4 v = src[i];
        m = max(m, __float_as_uint(fabsf(v.x)));
        m = max(m, __float_as_uint(fabsf(v.y)));
        m = max(m, __float_as_uint(fabsf(v.z)));
        m = max(m, __float_as_uint(fabsf(v.w)));
    }
#pragma unroll
    for (int o = 16; o > 0; o >>= 1)
        m = max(m, __shfl_xor_sync(0xffffffffu, m, o));
    __shared__ unsigned red[8];
    if ((threadIdx.x & 31) == 0) red[threadIdx.x >> 5] = m;
    __syncthreads();
    if (threadIdx.x == 0) {
        unsigned v = red[0];
#pragma unroll
        for (int i = 1; i < 8; ++i) v = max(v, red[i]);
        atomicMax(&g_amax[which], v);
    }
}

// ---------------------------------------------------------------------------
// Quantize to integer-valued bf16, pre-swizzled tile-major.
// q = clip(rint(v * 127/amax), -127, 127); rintf == jnp.round (half-even).
// ---------------------------------------------------------------------------
__device__ __forceinline__ float qval(float v, float s) {
    return fminf(127.f, fmaxf(-127.f, rintf(v * s)));
}
__device__ __forceinline__ uint32_t bf2(float lo, float hi) {
    uint32_t r;
    asm("cvt.rn.bf16x2.f32 %0, %1, %2;" : "=r"(r) : "f"(hi), "f"(lo));
    return r;
}
__device__ __forceinline__ uint4 pack8(float4 a, float4 b, float s) {
    uint4 q;
    q.x = bf2(qval(a.x, s), qval(a.y, s));
    q.y = bf2(qval(a.z, s), qval(a.w, s));
    q.z = bf2(qval(b.x, s), qval(b.y, s));
    q.w = bf2(qval(b.z, s), qval(b.w, s));
    return q;
}

// A: thread = (row r of 8192, 16B out-chunk cc of 512); 128-row blocks
__global__ void hx_quantA(const float4* __restrict__ x) {
    const int tid = blockIdx.x * blockDim.x + threadIdx.x;
    const int r = tid >> 9, cc = tid & 511;
    const float s = 127.0f / __uint_as_float(g_amax[0]);
    const float4* p = x + (size_t)r * 1024 + cc * 2;
    const uint4 q = pack8(p[0], p[1], s);
    const int mb = r >> 7, row = r & 127, kb = cc >> 3, c = cc & 7;
    const size_t off =
        ((size_t)((mb * 64 + kb) * 128 + row)) * 128 + ((c ^ (row & 7)) << 4);
    *reinterpret_cast<uint4*>(reinterpret_cast<char*>(g_qxb) + off) = q;
}

// B: thread = (row r of 4096, 16B out-chunk cc of 512); 128-row blocks
__global__ void hx_quantB(const float4* __restrict__ w) {
    const int tid = blockIdx.x * blockDim.x + threadIdx.x;
    const int r = tid >> 9, cc = tid & 511;
    const float s = 127.0f / __uint_as_float(g_amax[1]);
    const float4* p = w + (size_t)r * 1024 + cc * 2;
    const uint4 q = pack8(p[0], p[1], s);
    const int nb = r >> 7, row = r & 127, kb = cc >> 3, c = cc & 7;
    const size_t off =
        ((size_t)((nb * 64 + kb) * 128 + row)) * 128 + ((c ^ (row & 7)) << 4);
    *reinterpret_cast<uint4*>(reinterpret_cast<char*>(g_qwb) + off) = q;
}

// ---------------------------------------------------------------------------
// bf16 GEMM: HMMA m16n8k16 f32-accum, cp.async.bulk feed of pre-swizzled
// contiguous tiles. CTA 128x128, BK=64, 3 stages, 4 compute warps
// (warp tile 64x64) + 1 producer thread; 2 CTAs/SM.
// ---------------------------------------------------------------------------
__device__ __forceinline__ void ldsm4(uint32_t addr, uint32_t& r0, uint32_t& r1,
                                      uint32_t& r2, uint32_t& r3) {
    asm volatile("ldmatrix.sync.aligned.m8n8.x4.shared.b16 {%0,%1,%2,%3}, [%4];\n"
                 : "=r"(r0), "=r"(r1), "=r"(r2), "=r"(r3)
                 : "r"(addr));
}
__device__ __forceinline__ void hmma(float* c, const uint32_t* a, const uint32_t* b) {
    asm volatile(
        "mma.sync.aligned.m16n8k16.row.col.f32.bf16.bf16.f32 "
        "{%0,%1,%2,%3}, {%4,%5,%6,%7}, {%8,%9}, {%0,%1,%2,%3};\n"
        : "+f"(c[0]), "+f"(c[1]), "+f"(c[2]), "+f"(c[3])
        : "r"(a[0]), "r"(a[1]), "r"(a[2]), "r"(a[3]), "r"(b[0]), "r"(b[1]));
}
__device__ __forceinline__ void bar_init(uint32_t bar, uint32_t cnt) {
    asm volatile("mbarrier.init.shared.b64 [%0], %1;" ::"r"(bar), "r"(cnt) : "memory");
}
__device__ __forceinline__ void bar_arrive(uint32_t bar) {
    asm volatile("mbarrier.arrive.shared.b64 _, [%0];" ::"r"(bar) : "memory");
}
__device__ __forceinline__ void bar_expect_tx(uint32_t bar, uint32_t bytes) {
    asm volatile("mbarrier.arrive.expect_tx.shared.b64 _, [%0], %1;"
                 ::"r"(bar), "r"(bytes) : "memory");
}
__device__ __forceinline__ void bar_wait(uint32_t bar, uint32_t parity) {
    asm volatile(
        "{\n\t.reg .pred P;\n\t"
        "BW_%=:\n\t"
        "mbarrier.try_wait.parity.acquire.cta.shared::cta.b64 P, [%0], %1, 0x989680;\n\t"
        "@P bra.uni BD_%=;\n\t"
        "bra.uni BW_%=;\n\t"
        "BD_%=:\n\t}"
        ::"r"(bar), "r"(parity) : "memory");
}
__device__ __forceinline__ void bulk_cp(uint32_t dst, const void* src,
                                        uint32_t bytes, uint32_t bar) {
    asm volatile(
        "cp.async.bulk.shared::cluster.global.mbarrier::complete_tx::bytes "
        "[%0], [%1], %2, [%3];"
        ::"r"(dst), "l"(src), "r"(bytes), "r"(bar) : "memory");
}

__global__ void __launch_bounds__(160, 2)
hx_gemm(const float* __restrict__ bias, float* __restrict__ out) {
    extern __shared__ signed char smem[];
    __shared__ __align__(8) uint64_t s_bars[2 * NS];  // full[3], empty[3]

    const uint32_t sbase = (uint32_t)__cvta_generic_to_shared(smem);
    const uint32_t bar0 = (uint32_t)__cvta_generic_to_shared(&s_bars[0]);

    const int t = threadIdx.x;
    const int lane = t & 31;
    const int wid = t >> 5;
    const int m0 = blockIdx.y * BM;
    const int n0 = blockIdx.x * BN;

    if (t == 0) {
#pragma unroll
        for (int s = 0; s < NS; ++s) {
            bar_init(bar0 + 8 * s, 1);            // full[s]: producer expect_tx
            bar_init(bar0 + 8 * (NS + s), 128);   // empty[s]: 128 consumer arrivals
        }
    }
    __syncthreads();

    // ---------------- producer: thread 128 -----------------------------------
    if (t == 128) {
        const char* gA = reinterpret_cast<const char*>(g_qxb) +
                         (size_t)blockIdx.y * 64 * A_STAGE;
        const char* gB = reinterpret_cast<const char*>(g_qwb) +
                         (size_t)blockIdx.x * 64 * B_STAGE;
        int s = 0, ph = 1;
        for (int i = 0; i < NIT; ++i) {
            bar_wait(bar0 + 8 * (NS + s), (uint32_t)ph);  // empty[s]
            const uint32_t fb = bar0 + 8 * s;
            bar_expect_tx(fb, STAGE_BYTES_TX);
            const uint32_t ab = sbase + s * A_STAGE;
            const uint32_t bb = sbase + B_OFF + s * B_STAGE;
            const char* sa = gA + (size_t)i * A_STAGE;
            const char* sb = gB + (size_t)i * B_STAGE;
            bulk_cp(ab, sa, 8192, fb);
            bulk_cp(ab + 8192, sa + 8192, 8192, fb);
            bulk_cp(bb, sb, 8192, fb);
            bulk_cp(bb + 8192, sb + 8192, 8192, fb);
            if (++s == NS) { s = 0; ph ^= 1; }
        }
    }

    // ---------------- consumers: warps 0..3, warp tile 64x64 -----------------
    if (wid < 4) {
        const int wm = wid >> 1;  // 0..1
        const int wn = wid & 1;   // 0..1

        float acc[4][8][4];
#pragma unroll
        for (int a = 0; a < 4; ++a)
#pragma unroll
            for (int b = 0; b < 8; ++b)
#pragma unroll
                for (int r = 0; r < 4; ++r) acc[a][b][r] = 0.0f;

        int s = 0, ph = 0;
        for (int i = 0; i < NIT; ++i) {
            bar_wait(bar0 + 8 * s, (uint32_t)ph);  // full[s]
            const uint32_t abase = sbase + s * A_STAGE;
            const uint32_t bbase = sbase + B_OFF + s * B_STAGE;
#pragma unroll
            for (int ks = 0; ks < 4; ++ks) {  // 4 x k16 per BK=64
                uint32_t a[4][4];
#pragma unroll
                for (int mf = 0; mf < 4; ++mf) {
                    const int row =
                        wm * 64 + mf * 16 + (lane & 7) + ((lane >> 3) & 1) * 8;
                    const int kc = ks * 2 + (lane >> 4);  // 16B chunk
                    const uint32_t addr =
                        abase + row * 128 + ((kc ^ (row & 7)) << 4);
                    ldsm4(addr, a[mf][0], a[mf][1], a[mf][2], a[mf][3]);
                }
                uint32_t b[8][2];
#pragma unroll
                for (int p = 0; p < 4; ++p) {
                    const int nr = wn * 64 + (p * 2 + (lane >> 4)) * 8 + (lane & 7);
                    const int kc = ks * 2 + ((lane >> 3) & 1);
                    const uint32_t addr =
                        bbase + nr * 128 + ((kc ^ (nr & 7)) << 4);
                    ldsm4(addr, b[2 * p][0], b[2 * p][1], b[2 * p + 1][0],
                          b[2 * p + 1][1]);
                }
#pragma unroll
                for (int mf = 0; mf < 4; ++mf)
#pragma unroll
                    for (int nf = 0; nf < 8; ++nf) hmma(acc[mf][nf], a[mf], b[nf]);
            }
            bar_arrive(bar0 + 8 * (NS + s));  // empty[s]
            if (++s == NS) { s = 0; ph ^= 1; }
        }

        // ---- epilogue: out = acc * invd + bias (acc is integer-valued) ----
        const float sx = 127.0f / __uint_as_float(g_amax[0]);
        const float sw = 127.0f / __uint_as_float(g_amax[1]);
        const float invd = 1.0f / (sx * sw);

#pragma unroll
        for (int mf = 0; mf < 4; ++mf) {
            const int r0 = m0 + wm * 64 + mf * 16 + (lane >> 2);
#pragma unroll
            for (int nf = 0; nf < 8; ++nf) {
                const int cg = n0 + wn * 64 + nf * 8 + 2 * (lane & 3);
                const float2 bz = *reinterpret_cast<const float2*>(bias + cg);
                float2 o0, o1;
                o0.x = acc[mf][nf][0] * invd + bz.x;
                o0.y = acc[mf][nf][1] * invd + bz.y;
                o1.x = acc[mf][nf][2] * invd + bz.x;
                o1.y = acc[mf][nf][3] * invd + bz.y;
                *reinterpret_cast<float2*>(out + (size_t)r0 * N_DIM + cg) = o0;
                *reinterpret_cast<float2*>(out + (size_t)(r0 + 8) * N_DIM + cg) = o1;
            }
        }
    }
}

// ---------------------------------------------------------------------------
extern "C" void kernel_launch(void* const* d_in, const int* in_sizes, int n_in,
                              void* d_out, int out_size) {
    const float* x = (const float*)d_in[0];
    const float* w = (const float*)d_in[1];
    const float* bias = (const float*)d_in[2];
    float* out = (float*)d_out;
    (void)in_sizes; (void)n_in; (void)out_size;

    cudaFuncSetAttribute(hx_gemm, cudaFuncAttributeMaxDynamicSharedMemorySize,
                         SMEM_TC);

    hx_init<<<1, 1>>>();

    const int nx4 = (M_DIM * K_DIM) / 4;
    const int nw4 = (N_DIM * K_DIM) / 4;
    hx_amax<<<2048, 256>>>((const float4*)x, nx4, 0);
    hx_amax<<<1024, 256>>>((const float4*)w, nw4, 1);

    hx_quantA<<<(M_DIM * 512) / 256, 256>>>((const float4*)x);
    hx_quantB<<<(N_DIM * 512) / 256, 256>>>((const float4*)w);

    dim3 grid(N_DIM / BN, M_DIM / BM);  // (32, 64)
    hx_gemm<<<grid, 160, SMEM_TC>>>(bias, out);
}